// round 15
// baseline (speedup 1.0000x reference)
#include <cuda_runtime.h>
#include <cuda_fp16.h>

#define NROWS 32768
#define DDIM  64
#define KCB   1024
#define MT    128
#define NTILES 8
#define NTHREADS 256

#define O_ZQ    0
#define O_LOSS  2097152
#define O_PERP  2097153
#define O_IDX   2097154
#define O_DIST  2129922

// g1-only K layout: 64 halves + pad -> pitch 72 (word stride 36 -> conflict-free)
#define KP 72
#define B_TILE 18432               // 128 codes x 144 B
#define B_ALL  147456              // full codebook

// smem byte offsets
#define S_A     0                  // 128 x 144 = 18432
#define S_B     18432              // 147456 (whole codebook, resident)
#define S_E2    165888             // 1024 f32
#define S_F2    169984             // 128 f32
#define S_CAND  170496             // 128 rows x 16 slots x 8B = 16384
#define S_IDX   186880             // 128 i32
#define S_RED   187392             // 256 f32
#define S_STAGE 188416             // 64 x 140 f32 = 35840
#define SMEM_BYTES 224256

#define SPITCH 140                 // words; staging banks all distinct per warp

#define ESCALE 1024.0f
#define DSCALE (-2.0f / 1024.0f)   // exact power of two
#define MARGIN 6e-4f

__device__ float         g_loss;
__device__ unsigned int  g_counts[KCB];
__device__ float         g_e2[KCB];
__device__ __align__(16) unsigned char g_epack[B_ALL];

__device__ __forceinline__ unsigned smem_u32(const void* p) {
    unsigned a;
    asm("{ .reg .u64 t; cvta.to.shared.u64 t, %1; cvt.u32.u64 %0, t; }"
        : "=r"(a) : "l"(p));
    return a;
}
__device__ __forceinline__ void cp16(unsigned dst, const void* src) {
    asm volatile("cp.async.cg.shared.global [%0], [%1], 16;" :: "r"(dst), "l"(src));
}
#define CP_COMMIT() asm volatile("cp.async.commit_group;" ::: "memory")
#define CP_WAIT0()  asm volatile("cp.async.wait_group 0;"  ::: "memory")

__device__ __forceinline__ void mma16816(float* c, const unsigned* a,
                                         unsigned b0, unsigned b1) {
    asm volatile(
        "mma.sync.aligned.m16n8k16.row.col.f32.f16.f16.f32 "
        "{%0,%1,%2,%3}, {%4,%5,%6,%7}, {%8,%9}, {%0,%1,%2,%3};"
        : "+f"(c[0]), "+f"(c[1]), "+f"(c[2]), "+f"(c[3])
        : "r"(a[0]), "r"(a[1]), "r"(a[2]), "r"(a[3]), "r"(b0), "r"(b1));
}

// cooperative, aligned store of one 64-row half-tile from stage to gmem.
// gdst float-index is 2 mod 4, so gdst+2 is 16B-aligned; head/tail are 8B stores.
// staged column c of a row lives at word c+2 of that row.
__device__ __forceinline__ void coop_store_half(const float* stage,
                                                float* gdst, int t)
{
    const int lane16 = t & 15;
    const int rb = t >> 4;
    #pragma unroll
    for (int sweep = 0; sweep < 4; ++sweep) {
        const int r = sweep * 16 + rb;
        const float* srow = stage + r * SPITCH;
        float* grow = gdst + (size_t)r * KCB;
        int k = lane16;
        *(float4*)(grow + 2 + 4 * k) = *(const float4*)(srow + 4 + 4 * k);
        k = lane16 + 16;
        if (k < 31) {
            *(float4*)(grow + 2 + 4 * k) = *(const float4*)(srow + 4 + 4 * k);
        } else {   // lane16 == 15: head (cols 0,1) + tail (cols 126,127)
            *(float2*)(grow)       = *(const float2*)(srow + 2);
            *(float2*)(grow + 126) = *(const float2*)(srow + 128);
        }
    }
}

// ---- prepack: g1 = fp16(1024*emb) rows (pitch KP) + e2; block 64 zeroes scratch ----
__global__ void vq_prepack_kernel(const float* __restrict__ emb) {
    const int t = threadIdx.x;
    if (blockIdx.x == 64) {
        for (int i = t; i < KCB; i += NTHREADS) g_counts[i] = 0u;
        if (t == 0) g_loss = 0.0f;
        return;
    }
    const int kk = t >> 4, part = t & 15;
    const int k = blockIdx.x * 16 + kk;
    const float* ep = emb + (size_t)k * DDIM + part * 4;
    __half* row = (__half*)(g_epack + (size_t)k * (KP * 2));
    float e2p = 0.0f;
    #pragma unroll
    for (int i = 0; i < 4; i += 2) {
        float x0 = ep[i], x1 = ep[i + 1];
        e2p = fmaf(x0, x0, e2p);
        e2p = fmaf(x1, x1, e2p);
        __half a0 = __float2half_rn(x0 * ESCALE);
        __half a1 = __float2half_rn(x1 * ESCALE);
        *(__half2*)(row + part * 4 + i) = __halves2half2(a0, a1);
    }
    #pragma unroll
    for (int off = 8; off > 0; off >>= 1)
        e2p += __shfl_xor_sync(0xffffffffu, e2p, off, 16);
    if (part == 0) g_e2[k] = e2p;
}

__global__ void __launch_bounds__(NTHREADS, 1)
vq_main_kernel(const float* __restrict__ z_e,
               const float* __restrict__ emb,
               float* __restrict__ zq_out,
               float* __restrict__ idx_out,
               float* __restrict__ dist_out)
{
    extern __shared__ unsigned char smem[];
    const unsigned sbase = smem_u32(smem);
    const int t = threadIdx.x, lane = t & 31, w = t >> 5;
    const int wm = w & 3, wn = w >> 2;          // 4 row-quads x 2 col-halves
    const int q = lane & 3, lg = lane >> 2;

    const int n0 = blockIdx.x * MT, b = n0 >> 10, hw0 = n0 & 1023;
    const float* zbase = z_e + (size_t)b * (DDIM * 1024) + hw0;

    __half* A_s  = (__half*)(smem + S_A);
    float*  e2_s = (float*)(smem + S_E2);
    float*  f2_s = (float*)(smem + S_F2);
    float2* cand = (float2*)(smem + S_CAND);
    int*    idx_s = (int*)(smem + S_IDX);
    float*  red  = (float*)(smem + S_RED);
    float*  stage_s = (float*)(smem + S_STAGE);

    // load whole codebook-g1 into smem (36 x 16B per thread)
    #pragma unroll
    for (int i = 0; i < 36; ++i) {
        int c = i * NTHREADS + t;
        cp16(sbase + S_B + c * 16, g_epack + c * 16);
    }
    CP_COMMIT();

    // build A = h1 fp16 (pitch KP) + f2, strided direct loads
    {
        const int m = t >> 1, hf = t & 1;
        __half* arow = A_s + m * KP;
        float f2p = 0.0f;
        #pragma unroll
        for (int i = 0; i < 32; i += 2) {
            int d = hf * 32 + i;
            float x0 = zbase[(size_t)d * 1024 + m];
            float x1 = zbase[(size_t)(d + 1) * 1024 + m];
            f2p = fmaf(x0, x0, f2p);
            f2p = fmaf(x1, x1, f2p);
            *(__half2*)(arow + d) =
                __halves2half2(__float2half_rn(x0), __float2half_rn(x1));
        }
        float oth = __shfl_xor_sync(0xffffffffu, f2p, 1);
        if (hf == 0) f2_s[m] = f2p + oth;
    }
    #pragma unroll
    for (int i = 0; i < 4; ++i) e2_s[i * NTHREADS + t] = g_e2[i * NTHREADS + t];
    CP_WAIT0();
    __syncthreads();

    // per-(thread,row-instance) running top-2: ri = mt*2 + (0:row r, 1:row r+8)
    float v1[4], v2[4];
    int   i1[4], i2[4];
    #pragma unroll
    for (int i = 0; i < 4; ++i) { v1[i] = 3.0e38f; v2[i] = 3.0e38f; i1[i] = 0; i2[i] = 0; }

    const float f2a0 = f2_s[wm * 32 + lg];
    const float f2b0 = f2_s[wm * 32 + lg + 8];
    const float f2a1 = f2_s[wm * 32 + 16 + lg];
    const float f2b1 = f2_s[wm * 32 + 16 + lg + 8];

    #pragma unroll 1
    for (int t8 = 0; t8 < NTILES; ++t8) {
        const __half* B_s = (const __half*)(smem + S_B + t8 * B_TILE);

        float C[2][8][4];
        #pragma unroll
        for (int mt = 0; mt < 2; ++mt)
            #pragma unroll
            for (int nt = 0; nt < 8; ++nt)
                #pragma unroll
                for (int r = 0; r < 4; ++r) C[mt][nt][r] = 0.0f;

        #pragma unroll
        for (int kt = 0; kt < 4; ++kt) {
            const int k0 = kt * 16 + 2 * q;
            unsigned a[2][4];
            #pragma unroll
            for (int mt = 0; mt < 2; ++mt) {
                const int r = wm * 32 + mt * 16 + lg;
                a[mt][0] = *(const unsigned*)(A_s + r * KP + k0);
                a[mt][1] = *(const unsigned*)(A_s + (r + 8) * KP + k0);
                a[mt][2] = *(const unsigned*)(A_s + r * KP + k0 + 8);
                a[mt][3] = *(const unsigned*)(A_s + (r + 8) * KP + k0 + 8);
            }
            #pragma unroll
            for (int nt = 0; nt < 8; ++nt) {
                const int n = wn * 64 + nt * 8 + lg;
                unsigned b0 = *(const unsigned*)(B_s + n * KP + k0);
                unsigned b1 = *(const unsigned*)(B_s + n * KP + k0 + 8);
                mma16816(C[0][nt], a[0], b0, b1);
                mma16816(C[1][nt], a[1], b0, b1);
            }
        }

        // pass A: distances + top-2 for ALL warps; lower-half warps (wm<2) stage
        #pragma unroll
        for (int mt = 0; mt < 2; ++mt) {
            const int r = wm * 32 + mt * 16 + lg;
            const float f2a = mt ? f2a1 : f2a0;
            const float f2b = mt ? f2b1 : f2b0;
            const int ra = mt * 2, rb = mt * 2 + 1;
            #pragma unroll
            for (int nt = 0; nt < 8; ++nt) {
                const int coll = wn * 64 + nt * 8 + 2 * q;
                const int col = t8 * 128 + coll;
                const float e2x = e2_s[col], e2y = e2_s[col + 1];
                float d0 = fmaf(DSCALE, C[mt][nt][0], f2a + e2x);
                float d1 = fmaf(DSCALE, C[mt][nt][1], f2a + e2y);
                float d2 = fmaf(DSCALE, C[mt][nt][2], f2b + e2x);
                float d3 = fmaf(DSCALE, C[mt][nt][3], f2b + e2y);
                if (d0 < v1[ra]) { v2[ra]=v1[ra]; i2[ra]=i1[ra]; v1[ra]=d0; i1[ra]=col; }
                else if (d0 < v2[ra]) { v2[ra]=d0; i2[ra]=col; }
                if (d1 < v1[ra]) { v2[ra]=v1[ra]; i2[ra]=i1[ra]; v1[ra]=d1; i1[ra]=col+1; }
                else if (d1 < v2[ra]) { v2[ra]=d1; i2[ra]=col+1; }
                if (d2 < v1[rb]) { v2[rb]=v1[rb]; i2[rb]=i1[rb]; v1[rb]=d2; i1[rb]=col; }
                else if (d2 < v2[rb]) { v2[rb]=d2; i2[rb]=col; }
                if (d3 < v1[rb]) { v2[rb]=v1[rb]; i2[rb]=i1[rb]; v1[rb]=d3; i1[rb]=col+1; }
                else if (d3 < v2[rb]) { v2[rb]=d3; i2[rb]=col+1; }
                if (wm < 2) {
                    float* s0 = stage_s + (r & 63) * SPITCH + 2 + coll;
                    *(float2*)(s0)              = make_float2(d0, d1);
                    *(float2*)(s0 + 8 * SPITCH) = make_float2(d2, d3);
                }
            }
        }
        __syncthreads();
        coop_store_half(stage_s, dist_out + (size_t)n0 * KCB + t8 * 128, t);
        __syncthreads();

        // pass B: upper-half warps (wm>=2) stage (bit-identical recompute)
        if (wm >= 2) {
            #pragma unroll
            for (int mt = 0; mt < 2; ++mt) {
                const int r = wm * 32 + mt * 16 + lg;
                const float f2a = mt ? f2a1 : f2a0;
                const float f2b = mt ? f2b1 : f2b0;
                #pragma unroll
                for (int nt = 0; nt < 8; ++nt) {
                    const int coll = wn * 64 + nt * 8 + 2 * q;
                    const int col = t8 * 128 + coll;
                    const float e2x = e2_s[col], e2y = e2_s[col + 1];
                    float* s0 = stage_s + (r & 63) * SPITCH + 2 + coll;
                    *(float2*)(s0) = make_float2(
                        fmaf(DSCALE, C[mt][nt][0], f2a + e2x),
                        fmaf(DSCALE, C[mt][nt][1], f2a + e2y));
                    *(float2*)(s0 + 8 * SPITCH) = make_float2(
                        fmaf(DSCALE, C[mt][nt][2], f2b + e2x),
                        fmaf(DSCALE, C[mt][nt][3], f2b + e2y));
                }
            }
        }
        __syncthreads();
        coop_store_half(stage_s, dist_out + (size_t)(n0 + 64) * KCB + t8 * 128, t);
        __syncthreads();
    }

    // dump 16 candidate (v,i) slots per row to smem
    #pragma unroll
    for (int ri = 0; ri < 4; ++ri) {
        const int row = wm * 32 + (ri >> 1) * 16 + (ri & 1) * 8 + lg;
        const int base = row * 16 + wn * 8 + q * 2;
        cand[base]     = make_float2(v1[ri], __int_as_float(i1[ri]));
        cand[base + 1] = make_float2(v2[ri], __int_as_float(i2[ri]));
    }
    __syncthreads();

    // refine: one warp per 16 rows; exact fp32 re-check within MARGIN.
    // Exact s uses the SAME f2+e2-2dot formula as the stored distances so
    // fp32 rounding ties resolve identically (argmin tie -> lowest index).
    for (int j = 0; j < 16; ++j) {
        const int row = w * 16 + j;
        const float f2row = f2_s[row];
        float cv = 3.0e38f;
        int   ci = 0;
        if (lane < 16) {
            float2 e = cand[row * 16 + lane];
            cv = e.x;
            ci = __float_as_int(e.y);
        }
        float vmin = cv;
        #pragma unroll
        for (int off = 16; off > 0; off >>= 1)
            vmin = fminf(vmin, __shfl_xor_sync(0xffffffffu, vmin, off));
        unsigned mask = __ballot_sync(0xffffffffu, (lane < 16) && (cv <= vmin + MARGIN));
        int widx;
        if (__popc(mask) == 1) {
            widx = __shfl_sync(0xffffffffu, ci, __ffs(mask) - 1);
        } else {
            const int d0 = 2 * lane, d1 = 2 * lane + 1;
            const float z0 = zbase[(size_t)d0 * 1024 + row];
            const float z1 = zbase[(size_t)d1 * 1024 + row];
            float bs = 3.0e38f;
            int   bidx = 0x7fffffff;
            unsigned mm = mask;
            while (mm) {
                const int src = __ffs(mm) - 1;
                mm &= mm - 1;
                const int cidx = __shfl_sync(0xffffffffu, ci, src);
                const float* er = emb + (size_t)cidx * DDIM;
                float p = fmaf(z0, er[d0], z1 * er[d1]);
                #pragma unroll
                for (int off = 16; off > 0; off >>= 1)
                    p += __shfl_xor_sync(0xffffffffu, p, off);
                float s = fmaf(-2.0f, p, f2row + e2_s[cidx]);
                if (s < bs || (s == bs && cidx < bidx)) { bs = s; bidx = cidx; }
            }
            widx = bidx;
        }
        if (lane == 0) {
            idx_s[row] = widx;
            idx_out[n0 + row] = (float)widx;
            atomicAdd(&g_counts[widx], 1u);
        }
    }
    __syncthreads();

    // z_q gather/scatter + loss partial
    float lsum = 0.0f;
    {
        const int m = t >> 1, hf = t & 1;
        const int bi = idx_s[m];
        const float* erow = emb + (size_t)bi * DDIM;
        float* zq_base = zq_out + (size_t)b * (DDIM * 1024) + hw0;
        #pragma unroll
        for (int i = 0; i < 32; ++i) {
            int d = hf * 32 + i;
            float v  = erow[d];
            float fv = zbase[(size_t)d * 1024 + m];
            float df = v - fv;
            lsum = fmaf(df, df, lsum);
            zq_base[(size_t)d * 1024 + m] = v;
        }
    }
    red[t] = lsum;
    __syncthreads();
    #pragma unroll
    for (int s = 128; s > 0; s >>= 1) {
        if (t < s) red[t] += red[t + s];
        __syncthreads();
    }
    if (t == 0) atomicAdd(&g_loss, red[0]);
}

__global__ void vq_finalize_kernel(float* __restrict__ loss_out,
                                   float* __restrict__ perp_out)
{
    __shared__ float red[KCB];
    int t = threadIdx.x;
    float c = (float)g_counts[t];
    float p = c * (1.0f / (float)NROWS);
    red[t] = p * logf(p + 1e-10f);
    __syncthreads();
    #pragma unroll
    for (int s = KCB / 2; s > 0; s >>= 1) {
        if (t < s) red[t] += red[t + s];
        __syncthreads();
    }
    if (t == 0) {
        *perp_out = expf(-red[0]);
        *loss_out = g_loss * (1.25f / (float)(NROWS * DDIM));
    }
}

extern "C" void kernel_launch(void* const* d_in, const int* in_sizes, int n_in,
                              void* d_out, int out_size)
{
    const float* z_e = (const float*)d_in[0];
    const float* emb = (const float*)d_in[1];
    float* out = (float*)d_out;

    cudaFuncSetAttribute(vq_main_kernel,
                         cudaFuncAttributeMaxDynamicSharedMemorySize, SMEM_BYTES);

    vq_prepack_kernel<<<65, NTHREADS>>>(emb);
    vq_main_kernel<<<NROWS / MT, NTHREADS, SMEM_BYTES>>>(
        z_e, emb, out + O_ZQ, out + O_IDX, out + O_DIST);
    vq_finalize_kernel<<<1, KCB>>>(out + O_LOSS, out + O_PERP);
}

// round 16
// speedup vs baseline: 1.4069x; 1.4069x over previous
#include <cuda_runtime.h>
#include <cuda_fp16.h>

#define NROWS 32768
#define DDIM  64
#define KCB   1024
#define MTU   32                   // rows per work unit
#define NU    (NROWS / MTU)        // 1024 units
#define NTILES 8
#define NTHREADS 512
#define GRID  148

#define O_ZQ    0
#define O_LOSS  2097152
#define O_PERP  2097153
#define O_IDX   2097154
#define O_DIST  2129922

// g1-only K layout: 64 halves + pad -> pitch 72 (conflict-free frag loads)
#define KP 72
#define B_TILE 18432               // 128 codes x 144 B
#define B_ALL  147456              // full codebook

// smem byte offsets
#define S_A     0                  // 4 groups x 4608 (32 rows x 144 B)
#define S_B     18432              // 147456 (codebook resident)
#define S_E2    165888             // 1024 f32
#define S_F2    169984             // 4 x 32 f32 = 512
#define S_CAND  170496             // 4 x (32 rows x 32 slots x 8B) = 32768
#define S_IDX   203264             // 4 x 32 i32 = 512
#define S_RED   203776             // 4 x 4 f32 = 64
#define S_U     203840             // 4 x i32 = 16
#define SMEM_BYTES 203904

#define ESCALE 1024.0f
#define DSCALE (-2.0f / 1024.0f)   // exact power of two
#define MARGIN 6e-4f

__device__ float         g_loss;
__device__ unsigned int  g_counts[KCB];
__device__ float         g_e2[KCB];
__device__ int           g_ctr;
__device__ __align__(16) unsigned char g_epack[B_ALL];

__device__ __forceinline__ unsigned smem_u32(const void* p) {
    unsigned a;
    asm("{ .reg .u64 t; cvta.to.shared.u64 t, %1; cvt.u32.u64 %0, t; }"
        : "=r"(a) : "l"(p));
    return a;
}
__device__ __forceinline__ void cp16(unsigned dst, const void* src) {
    asm volatile("cp.async.cg.shared.global [%0], [%1], 16;" :: "r"(dst), "l"(src));
}
#define CP_COMMIT() asm volatile("cp.async.commit_group;" ::: "memory")
#define CP_WAIT0()  asm volatile("cp.async.wait_group 0;"  ::: "memory")
#define GBAR(id)    asm volatile("bar.sync %0, 128;" :: "r"(id) : "memory")

__device__ __forceinline__ void mma16816(float* c, const unsigned* a,
                                         unsigned b0, unsigned b1) {
    asm volatile(
        "mma.sync.aligned.m16n8k16.row.col.f32.f16.f16.f32 "
        "{%0,%1,%2,%3}, {%4,%5,%6,%7}, {%8,%9}, {%0,%1,%2,%3};"
        : "+f"(c[0]), "+f"(c[1]), "+f"(c[2]), "+f"(c[3])
        : "r"(a[0]), "r"(a[1]), "r"(a[2]), "r"(a[3]), "r"(b0), "r"(b1));
}

// ---- prepack: g1 = fp16(1024*emb) rows (pitch KP) + e2; block 64 zeroes scratch ----
__global__ void vq_prepack_kernel(const float* __restrict__ emb) {
    const int t = threadIdx.x;
    if (blockIdx.x == 64) {
        for (int i = t; i < KCB; i += 256) g_counts[i] = 0u;
        if (t == 0) { g_loss = 0.0f; g_ctr = 0; }
        return;
    }
    const int kk = t >> 4, part = t & 15;
    const int k = blockIdx.x * 16 + kk;
    const float* ep = emb + (size_t)k * DDIM + part * 4;
    __half* row = (__half*)(g_epack + (size_t)k * (KP * 2));
    float e2p = 0.0f;
    #pragma unroll
    for (int i = 0; i < 4; i += 2) {
        float x0 = ep[i], x1 = ep[i + 1];
        e2p = fmaf(x0, x0, e2p);
        e2p = fmaf(x1, x1, e2p);
        __half a0 = __float2half_rn(x0 * ESCALE);
        __half a1 = __float2half_rn(x1 * ESCALE);
        *(__half2*)(row + part * 4 + i) = __halves2half2(a0, a1);
    }
    #pragma unroll
    for (int off = 8; off > 0; off >>= 1)
        e2p += __shfl_xor_sync(0xffffffffu, e2p, off, 16);
    if (part == 0) g_e2[k] = e2p;
}

// ---- main: persistent CTAs, 4 warp-groups, dynamic 32-row units ----
__global__ void __launch_bounds__(NTHREADS, 1)
vq_main_kernel(const float* __restrict__ z_e,
               const float* __restrict__ emb,
               float* __restrict__ zq_out,
               float* __restrict__ idx_out,
               float* __restrict__ dist_out)
{
    extern __shared__ unsigned char smem[];
    const unsigned sbase = smem_u32(smem);
    const int t = threadIdx.x, lane = t & 31;
    const int g = t >> 7, gt = t & 127, gw = gt >> 5;   // group, in-group tid, warp(=wn)
    const int q = lane & 3, lg = lane >> 2;
    const int barid = g + 1;

    float* e2_s = (float*)(smem + S_E2);
    __half* A_g  = (__half*)(smem + S_A + g * 4608);
    float*  f2_g = (float*)(smem + S_F2 + g * 128);
    float2* cand_g = (float2*)(smem + S_CAND + g * 8192);
    int*    idx_g  = (int*)(smem + S_IDX + g * 128);
    float*  red_g  = (float*)(smem + S_RED + g * 16);
    int*    u_g    = (int*)(smem + S_U + g * 4);

    // once per CTA: codebook + e2 resident
    #pragma unroll
    for (int i = 0; i < 18; ++i) {
        int c = i * NTHREADS + t;
        cp16(sbase + S_B + c * 16, g_epack + c * 16);
    }
    CP_COMMIT();
    e2_s[t] = g_e2[t];
    e2_s[NTHREADS + t] = g_e2[NTHREADS + t];
    CP_WAIT0();
    __syncthreads();

    while (true) {
        if (gt == 0) *u_g = atomicAdd(&g_ctr, 1);
        GBAR(barid);
        const int u = *u_g;
        if (u >= NU) break;
        const int rows0 = u * MTU;
        const int b = rows0 >> 10, hw0 = rows0 & 1023;
        const float* zbase = z_e + (size_t)b * (DDIM * 1024) + hw0;

        // A build + f2: m = gt>>2 (0..31), part = gt&3 (16 d's each)
        {
            const int m = gt >> 2, part = gt & 3;
            __half* arow = A_g + m * KP;
            float f2p = 0.0f;
            #pragma unroll
            for (int i = 0; i < 16; i += 2) {
                int d = part * 16 + i;
                float x0 = zbase[(size_t)d * 1024 + m];
                float x1 = zbase[(size_t)(d + 1) * 1024 + m];
                f2p = fmaf(x0, x0, f2p);
                f2p = fmaf(x1, x1, f2p);
                *(__half2*)(arow + d) =
                    __halves2half2(__float2half_rn(x0), __float2half_rn(x1));
            }
            f2p += __shfl_xor_sync(0xffffffffu, f2p, 1, 4);
            f2p += __shfl_xor_sync(0xffffffffu, f2p, 2, 4);
            if (part == 0) f2_g[m] = f2p;
        }
        GBAR(barid);

        float v1[4], v2[4];
        int   i1[4], i2[4];
        #pragma unroll
        for (int i = 0; i < 4; ++i) { v1[i] = 3.0e38f; v2[i] = 3.0e38f; i1[i] = 0; i2[i] = 0; }

        const float f2a0 = f2_g[lg];
        const float f2b0 = f2_g[lg + 8];
        const float f2a1 = f2_g[16 + lg];
        const float f2b1 = f2_g[24 + lg];

        #pragma unroll 1
        for (int t8 = 0; t8 < NTILES; ++t8) {
            const __half* B_s = (const __half*)(smem + S_B + t8 * B_TILE);

            float C[2][4][4];
            #pragma unroll
            for (int mt = 0; mt < 2; ++mt)
                #pragma unroll
                for (int nt = 0; nt < 4; ++nt)
                    #pragma unroll
                    for (int r = 0; r < 4; ++r) C[mt][nt][r] = 0.0f;

            #pragma unroll
            for (int kt = 0; kt < 4; ++kt) {
                const int k0 = kt * 16 + 2 * q;
                unsigned a[2][4];
                #pragma unroll
                for (int mt = 0; mt < 2; ++mt) {
                    const int r = mt * 16 + lg;
                    a[mt][0] = *(const unsigned*)(A_g + r * KP + k0);
                    a[mt][1] = *(const unsigned*)(A_g + (r + 8) * KP + k0);
                    a[mt][2] = *(const unsigned*)(A_g + r * KP + k0 + 8);
                    a[mt][3] = *(const unsigned*)(A_g + (r + 8) * KP + k0 + 8);
                }
                #pragma unroll
                for (int nt = 0; nt < 4; ++nt) {
                    const int n = gw * 32 + nt * 8 + lg;
                    unsigned b0 = *(const unsigned*)(B_s + n * KP + k0);
                    unsigned b1 = *(const unsigned*)(B_s + n * KP + k0 + 8);
                    mma16816(C[0][nt], a[0], b0, b1);
                    mma16816(C[1][nt], a[1], b0, b1);
                }
            }

            // epilogue: distances, top-2, direct float2 stores (R9 pattern)
            #pragma unroll
            for (int mt = 0; mt < 2; ++mt) {
                const int r = mt * 16 + lg;
                const float f2a = mt ? f2a1 : f2a0;
                const float f2b = mt ? f2b1 : f2b0;
                const int ra = mt * 2, rb = mt * 2 + 1;
                float* dra = dist_out + (size_t)(rows0 + r) * KCB;
                float* drb = dist_out + (size_t)(rows0 + r + 8) * KCB;
                #pragma unroll
                for (int nt = 0; nt < 4; ++nt) {
                    const int col = t8 * 128 + gw * 32 + nt * 8 + 2 * q;
                    const float e2x = e2_s[col], e2y = e2_s[col + 1];
                    float d0 = fmaf(DSCALE, C[mt][nt][0], f2a + e2x);
                    float d1 = fmaf(DSCALE, C[mt][nt][1], f2a + e2y);
                    float d2 = fmaf(DSCALE, C[mt][nt][2], f2b + e2x);
                    float d3 = fmaf(DSCALE, C[mt][nt][3], f2b + e2y);
                    if (d0 < v1[ra]) { v2[ra]=v1[ra]; i2[ra]=i1[ra]; v1[ra]=d0; i1[ra]=col; }
                    else if (d0 < v2[ra]) { v2[ra]=d0; i2[ra]=col; }
                    if (d1 < v1[ra]) { v2[ra]=v1[ra]; i2[ra]=i1[ra]; v1[ra]=d1; i1[ra]=col+1; }
                    else if (d1 < v2[ra]) { v2[ra]=d1; i2[ra]=col+1; }
                    if (d2 < v1[rb]) { v2[rb]=v1[rb]; i2[rb]=i1[rb]; v1[rb]=d2; i1[rb]=col; }
                    else if (d2 < v2[rb]) { v2[rb]=d2; i2[rb]=col; }
                    if (d3 < v1[rb]) { v2[rb]=v1[rb]; i2[rb]=i1[rb]; v1[rb]=d3; i1[rb]=col+1; }
                    else if (d3 < v2[rb]) { v2[rb]=d3; i2[rb]=col+1; }
                    *(float2*)(dra + col) = make_float2(d0, d1);
                    *(float2*)(drb + col) = make_float2(d2, d3);
                }
            }
        }

        // dump 32 candidate slots per row
        #pragma unroll
        for (int ri = 0; ri < 4; ++ri) {
            const int row = (ri >> 1) * 16 + (ri & 1) * 8 + lg;
            const int base = row * 32 + gw * 8 + q * 2;
            cand_g[base]     = make_float2(v1[ri], __int_as_float(i1[ri]));
            cand_g[base + 1] = make_float2(v2[ri], __int_as_float(i2[ri]));
        }
        GBAR(barid);

        // refine: warp gw handles rows gw*8..+7; 32 slots = one per lane.
        // Exact s uses the SAME f2+e2-2dot formula as stored distances so
        // fp32 rounding ties resolve identically (argmin tie -> lowest index).
        for (int j = 0; j < 8; ++j) {
            const int row = gw * 8 + j;
            const float f2row = f2_g[row];
            float2 e = cand_g[row * 32 + lane];
            float cv = e.x;
            int   ci = __float_as_int(e.y);
            float vmin = cv;
            #pragma unroll
            for (int off = 16; off > 0; off >>= 1)
                vmin = fminf(vmin, __shfl_xor_sync(0xffffffffu, vmin, off));
            unsigned mask = __ballot_sync(0xffffffffu, cv <= vmin + MARGIN);
            int widx;
            if (__popc(mask) == 1) {
                widx = __shfl_sync(0xffffffffu, ci, __ffs(mask) - 1);
            } else {
                const int d0 = 2 * lane, d1 = 2 * lane + 1;
                const float z0 = zbase[(size_t)d0 * 1024 + row];
                const float z1 = zbase[(size_t)d1 * 1024 + row];
                float bs = 3.0e38f;
                int   bidx = 0x7fffffff;
                unsigned mm = mask;
                while (mm) {
                    const int src = __ffs(mm) - 1;
                    mm &= mm - 1;
                    const int cidx = __shfl_sync(0xffffffffu, ci, src);
                    const float* er = emb + (size_t)cidx * DDIM;
                    float p = fmaf(z0, er[d0], z1 * er[d1]);
                    #pragma unroll
                    for (int off = 16; off > 0; off >>= 1)
                        p += __shfl_xor_sync(0xffffffffu, p, off);
                    float s = fmaf(-2.0f, p, f2row + e2_s[cidx]);
                    if (s < bs || (s == bs && cidx < bidx)) { bs = s; bidx = cidx; }
                }
                widx = bidx;
            }
            if (lane == 0) {
                idx_g[row] = widx;
                idx_out[rows0 + row] = (float)widx;
                atomicAdd(&g_counts[widx], 1u);
            }
        }
        GBAR(barid);

        // z_q gather/scatter + loss partial (group-local)
        float lsum = 0.0f;
        {
            float* zq_base = zq_out + (size_t)b * (DDIM * 1024) + hw0;
            #pragma unroll
            for (int it = 0; it < 16; ++it) {
                int li = it * 128 + gt, d = li >> 5, m = li & 31;
                float v  = emb[(size_t)idx_g[m] * DDIM + d];
                float fv = zbase[(size_t)d * 1024 + m];
                float df = v - fv;
                lsum = fmaf(df, df, lsum);
                zq_base[(size_t)d * 1024 + m] = v;
            }
        }
        #pragma unroll
        for (int off = 16; off > 0; off >>= 1)
            lsum += __shfl_xor_sync(0xffffffffu, lsum, off);
        if (lane == 0) red_g[gw] = lsum;
        GBAR(barid);
        if (gt == 0)
            atomicAdd(&g_loss, red_g[0] + red_g[1] + red_g[2] + red_g[3]);
    }
}

__global__ void vq_finalize_kernel(float* __restrict__ loss_out,
                                   float* __restrict__ perp_out)
{
    __shared__ float red[KCB];
    int t = threadIdx.x;
    float c = (float)g_counts[t];
    float p = c * (1.0f / (float)NROWS);
    red[t] = p * logf(p + 1e-10f);
    __syncthreads();
    #pragma unroll
    for (int s = KCB / 2; s > 0; s >>= 1) {
        if (t < s) red[t] += red[t + s];
        __syncthreads();
    }
    if (t == 0) {
        *perp_out = expf(-red[0]);
        *loss_out = g_loss * (1.25f / (float)(NROWS * DDIM));
    }
}

extern "C" void kernel_launch(void* const* d_in, const int* in_sizes, int n_in,
                              void* d_out, int out_size)
{
    const float* z_e = (const float*)d_in[0];
    const float* emb = (const float*)d_in[1];
    float* out = (float*)d_out;

    cudaFuncSetAttribute(vq_main_kernel,
                         cudaFuncAttributeMaxDynamicSharedMemorySize, SMEM_BYTES);

    vq_prepack_kernel<<<65, 256>>>(emb);
    vq_main_kernel<<<GRID, NTHREADS, SMEM_BYTES>>>(
        z_e, emb, out + O_ZQ, out + O_IDX, out + O_DIST);
    vq_finalize_kernel<<<1, KCB>>>(out + O_LOSS, out + O_PERP);
}

// round 17
// speedup vs baseline: 1.6867x; 1.1989x over previous
#include <cuda_runtime.h>
#include <cuda_fp16.h>

#define NROWS 32768
#define DDIM  64
#define KCB   1024
#define MTU   16                   // rows per work unit
#define NU    (NROWS / MTU)        // 2048 units
#define NTILES 8
#define NTHREADS 512
#define GRID  148

#define O_ZQ    0
#define O_LOSS  2097152
#define O_PERP  2097153
#define O_IDX   2097154
#define O_DIST  2129922

// g1-only K layout: 64 halves + pad -> pitch 72 (conflict-free frag loads)
#define KP 72
#define B_TILE 18432               // 128 codes x 144 B
#define B_ALL  147456              // full codebook

// smem byte offsets
#define S_A     0                  // 4 groups x 2304 (16 rows x 144 B) = 9216
#define S_B     9216               // 147456 (codebook resident)
#define S_E2    156672             // 1024 f32
#define S_F2    160768             // 4 x 16 f32 = 256
#define S_CAND  161024             // 4 x (16 rows x 32 slots x 8B) = 16384
#define S_IDX   177408             // 4 x 16 i32 = 256
#define S_RED   177664             // 4 x 4 f32 = 64
#define S_U     177728             // 4 x i32 = 16
#define SMEM_BYTES 177792

#define ESCALE 1024.0f
#define DSCALE (-2.0f / 1024.0f)   // exact power of two
#define MARGIN 6e-4f

__device__ float         g_loss;
__device__ unsigned int  g_counts[KCB];
__device__ float         g_e2[KCB];
__device__ int           g_ctr;
__device__ __align__(16) unsigned char g_epack[B_ALL];

__device__ __forceinline__ unsigned smem_u32(const void* p) {
    unsigned a;
    asm("{ .reg .u64 t; cvta.to.shared.u64 t, %1; cvt.u32.u64 %0, t; }"
        : "=r"(a) : "l"(p));
    return a;
}
__device__ __forceinline__ void cp16(unsigned dst, const void* src) {
    asm volatile("cp.async.cg.shared.global [%0], [%1], 16;" :: "r"(dst), "l"(src));
}
#define CP_COMMIT() asm volatile("cp.async.commit_group;" ::: "memory")
#define CP_WAIT0()  asm volatile("cp.async.wait_group 0;"  ::: "memory")
#define GBAR(id)    asm volatile("bar.sync %0, 128;" :: "r"(id) : "memory")

__device__ __forceinline__ void mma16816(float* c, const unsigned* a,
                                         unsigned b0, unsigned b1) {
    asm volatile(
        "mma.sync.aligned.m16n8k16.row.col.f32.f16.f16.f32 "
        "{%0,%1,%2,%3}, {%4,%5,%6,%7}, {%8,%9}, {%0,%1,%2,%3};"
        : "+f"(c[0]), "+f"(c[1]), "+f"(c[2]), "+f"(c[3])
        : "r"(a[0]), "r"(a[1]), "r"(a[2]), "r"(a[3]), "r"(b0), "r"(b1));
}

// ---- prepack: UNCHANGED e2 arithmetic (bit-identical; protects reference ties) ----
__global__ void vq_prepack_kernel(const float* __restrict__ emb) {
    const int t = threadIdx.x;
    if (blockIdx.x == 64) {
        for (int i = t; i < KCB; i += 256) g_counts[i] = 0u;
        if (t == 0) { g_loss = 0.0f; g_ctr = 0; }
        return;
    }
    const int kk = t >> 4, part = t & 15;
    const int k = blockIdx.x * 16 + kk;
    const float* ep = emb + (size_t)k * DDIM + part * 4;
    __half* row = (__half*)(g_epack + (size_t)k * (KP * 2));
    float e2p = 0.0f;
    #pragma unroll
    for (int i = 0; i < 4; i += 2) {
        float x0 = ep[i], x1 = ep[i + 1];
        e2p = fmaf(x0, x0, e2p);
        e2p = fmaf(x1, x1, e2p);
        __half a0 = __float2half_rn(x0 * ESCALE);
        __half a1 = __float2half_rn(x1 * ESCALE);
        *(__half2*)(row + part * 4 + i) = __halves2half2(a0, a1);
    }
    #pragma unroll
    for (int off = 8; off > 0; off >>= 1)
        e2p += __shfl_xor_sync(0xffffffffu, e2p, off, 16);
    if (part == 0) g_e2[k] = e2p;
}

// ---- main: persistent CTAs, 4 warp-groups, dynamic 16-row units ----
__global__ void __launch_bounds__(NTHREADS, 1)
vq_main_kernel(const float* __restrict__ z_e,
               const float* __restrict__ emb,
               float* __restrict__ zq_out,
               float* __restrict__ idx_out,
               float* __restrict__ dist_out)
{
    extern __shared__ unsigned char smem[];
    const unsigned sbase = smem_u32(smem);
    const int t = threadIdx.x, lane = t & 31;
    const int g = t >> 7, gt = t & 127, gw = gt >> 5;   // group, in-group tid, warp(=col quarter)
    const int q = lane & 3, lg = lane >> 2;
    const int barid = g + 1;

    float* e2_s = (float*)(smem + S_E2);
    __half* A_g  = (__half*)(smem + S_A + g * 2304);
    float*  f2_g = (float*)(smem + S_F2 + g * 64);
    float2* cand_g = (float2*)(smem + S_CAND + g * 4096);
    int*    idx_g  = (int*)(smem + S_IDX + g * 64);
    float*  red_g  = (float*)(smem + S_RED + g * 16);
    int*    u_g    = (int*)(smem + S_U + g * 4);

    // once per CTA: codebook + e2 resident
    #pragma unroll
    for (int i = 0; i < 18; ++i) {
        int c = i * NTHREADS + t;
        cp16(sbase + S_B + c * 16, g_epack + c * 16);
    }
    CP_COMMIT();
    e2_s[t] = g_e2[t];
    e2_s[NTHREADS + t] = g_e2[NTHREADS + t];
    CP_WAIT0();
    __syncthreads();

    while (true) {
        if (gt == 0) *u_g = atomicAdd(&g_ctr, 1);
        GBAR(barid);
        const int u = *u_g;
        if (u >= NU) break;
        const int rows0 = u * MTU;
        const int b = rows0 >> 10, hw0 = rows0 & 1023;
        const float* zbase = z_e + (size_t)b * (DDIM * 1024) + hw0;

        // A build + f2: m = gt>>3 (0..15), part = gt&7 (8 d's each)
        {
            const int m = gt >> 3, part = gt & 7;
            __half* arow = A_g + m * KP;
            float f2p = 0.0f;
            #pragma unroll
            for (int i = 0; i < 8; i += 2) {
                int d = part * 8 + i;
                float x0 = zbase[(size_t)d * 1024 + m];
                float x1 = zbase[(size_t)(d + 1) * 1024 + m];
                f2p = fmaf(x0, x0, f2p);
                f2p = fmaf(x1, x1, f2p);
                *(__half2*)(arow + d) =
                    __halves2half2(__float2half_rn(x0), __float2half_rn(x1));
            }
            f2p += __shfl_xor_sync(0xffffffffu, f2p, 1, 8);
            f2p += __shfl_xor_sync(0xffffffffu, f2p, 2, 8);
            f2p += __shfl_xor_sync(0xffffffffu, f2p, 4, 8);
            if (part == 0) f2_g[m] = f2p;
        }
        GBAR(barid);

        float v1[2], v2[2];
        int   i1[2], i2[2];
        #pragma unroll
        for (int i = 0; i < 2; ++i) { v1[i] = 3.0e38f; v2[i] = 3.0e38f; i1[i] = 0; i2[i] = 0; }

        const float f2a = f2_g[lg];
        const float f2b = f2_g[lg + 8];

        #pragma unroll 1
        for (int t8 = 0; t8 < NTILES; ++t8) {
            const __half* B_s = (const __half*)(smem + S_B + t8 * B_TILE);

            float C[4][4];
            #pragma unroll
            for (int nt = 0; nt < 4; ++nt)
                #pragma unroll
                for (int r = 0; r < 4; ++r) C[nt][r] = 0.0f;

            #pragma unroll
            for (int kt = 0; kt < 4; ++kt) {
                const int k0 = kt * 16 + 2 * q;
                unsigned a[4];
                a[0] = *(const unsigned*)(A_g + lg * KP + k0);
                a[1] = *(const unsigned*)(A_g + (lg + 8) * KP + k0);
                a[2] = *(const unsigned*)(A_g + lg * KP + k0 + 8);
                a[3] = *(const unsigned*)(A_g + (lg + 8) * KP + k0 + 8);
                #pragma unroll
                for (int nt = 0; nt < 4; ++nt) {
                    const int n = gw * 32 + nt * 8 + lg;
                    unsigned b0 = *(const unsigned*)(B_s + n * KP + k0);
                    unsigned b1 = *(const unsigned*)(B_s + n * KP + k0 + 8);
                    mma16816(C[nt], a, b0, b1);
                }
            }

            // epilogue: distances, top-2, direct float2 stores
            float* dra = dist_out + (size_t)(rows0 + lg) * KCB;
            float* drb = dist_out + (size_t)(rows0 + lg + 8) * KCB;
            #pragma unroll
            for (int nt = 0; nt < 4; ++nt) {
                const int col = t8 * 128 + gw * 32 + nt * 8 + 2 * q;
                const float e2x = e2_s[col], e2y = e2_s[col + 1];
                float d0 = fmaf(DSCALE, C[nt][0], f2a + e2x);
                float d1 = fmaf(DSCALE, C[nt][1], f2a + e2y);
                float d2 = fmaf(DSCALE, C[nt][2], f2b + e2x);
                float d3 = fmaf(DSCALE, C[nt][3], f2b + e2y);
                if (d0 < v1[0]) { v2[0]=v1[0]; i2[0]=i1[0]; v1[0]=d0; i1[0]=col; }
                else if (d0 < v2[0]) { v2[0]=d0; i2[0]=col; }
                if (d1 < v1[0]) { v2[0]=v1[0]; i2[0]=i1[0]; v1[0]=d1; i1[0]=col+1; }
                else if (d1 < v2[0]) { v2[0]=d1; i2[0]=col+1; }
                if (d2 < v1[1]) { v2[1]=v1[1]; i2[1]=i1[1]; v1[1]=d2; i1[1]=col; }
                else if (d2 < v2[1]) { v2[1]=d2; i2[1]=col; }
                if (d3 < v1[1]) { v2[1]=v1[1]; i2[1]=i1[1]; v1[1]=d3; i1[1]=col+1; }
                else if (d3 < v2[1]) { v2[1]=d3; i2[1]=col+1; }
                *(float2*)(dra + col) = make_float2(d0, d1);
                *(float2*)(drb + col) = make_float2(d2, d3);
            }
        }

        // dump 32 candidate slots per row
        #pragma unroll
        for (int ri = 0; ri < 2; ++ri) {
            const int row = ri * 8 + lg;
            const int base = row * 32 + gw * 8 + q * 2;
            cand_g[base]     = make_float2(v1[ri], __int_as_float(i1[ri]));
            cand_g[base + 1] = make_float2(v2[ri], __int_as_float(i2[ri]));
        }
        GBAR(barid);

        // refine: warp gw handles rows gw*4..+3; 32 slots = one per lane.
        // Exact s uses the SAME f2+e2-2dot formula as stored distances so
        // fp32 rounding ties resolve identically (argmin tie -> lowest index).
        for (int j = 0; j < 4; ++j) {
            const int row = gw * 4 + j;
            const float f2row = f2_g[row];
            float2 e = cand_g[row * 32 + lane];
            float cv = e.x;
            int   ci = __float_as_int(e.y);
            float vmin = cv;
            #pragma unroll
            for (int off = 16; off > 0; off >>= 1)
                vmin = fminf(vmin, __shfl_xor_sync(0xffffffffu, vmin, off));
            unsigned mask = __ballot_sync(0xffffffffu, cv <= vmin + MARGIN);
            int widx;
            if (__popc(mask) == 1) {
                widx = __shfl_sync(0xffffffffu, ci, __ffs(mask) - 1);
            } else {
                const int d0 = 2 * lane, d1 = 2 * lane + 1;
                const float z0 = zbase[(size_t)d0 * 1024 + row];
                const float z1 = zbase[(size_t)d1 * 1024 + row];
                float bs = 3.0e38f;
                int   bidx = 0x7fffffff;
                unsigned mm = mask;
                while (mm) {
                    const int src = __ffs(mm) - 1;
                    mm &= mm - 1;
                    const int cidx = __shfl_sync(0xffffffffu, ci, src);
                    const float* er = emb + (size_t)cidx * DDIM;
                    float p = fmaf(z0, er[d0], z1 * er[d1]);
                    #pragma unroll
                    for (int off = 16; off > 0; off >>= 1)
                        p += __shfl_xor_sync(0xffffffffu, p, off);
                    float s = fmaf(-2.0f, p, f2row + e2_s[cidx]);
                    if (s < bs || (s == bs && cidx < bidx)) { bs = s; bidx = cidx; }
                }
                widx = bidx;
            }
            if (lane == 0) {
                idx_g[row] = widx;
                idx_out[rows0 + row] = (float)widx;
                atomicAdd(&g_counts[widx], 1u);
            }
        }
        GBAR(barid);

        // z_q gather/scatter + loss partial (group-local; 16 rows x 64 d)
        float lsum = 0.0f;
        {
            float* zq_base = zq_out + (size_t)b * (DDIM * 1024) + hw0;
            #pragma unroll
            for (int it = 0; it < 8; ++it) {
                int li = it * 128 + gt, d = li >> 4, m = li & 15;
                float v  = emb[(size_t)idx_g[m] * DDIM + d];
                float fv = zbase[(size_t)d * 1024 + m];
                float df = v - fv;
                lsum = fmaf(df, df, lsum);
                zq_base[(size_t)d * 1024 + m] = v;
            }
        }
        #pragma unroll
        for (int off = 16; off > 0; off >>= 1)
            lsum += __shfl_xor_sync(0xffffffffu, lsum, off);
        if (lane == 0) red_g[gw] = lsum;
        GBAR(barid);
        if (gt == 0)
            atomicAdd(&g_loss, red_g[0] + red_g[1] + red_g[2] + red_g[3]);
    }
}

__global__ void vq_finalize_kernel(float* __restrict__ loss_out,
                                   float* __restrict__ perp_out)
{
    __shared__ float red[KCB];
    int t = threadIdx.x;
    float c = (float)g_counts[t];
    float p = c * (1.0f / (float)NROWS);
    red[t] = p * logf(p + 1e-10f);
    __syncthreads();
    #pragma unroll
    for (int s = KCB / 2; s > 0; s >>= 1) {
        if (t < s) red[t] += red[t + s];
        __syncthreads();
    }
    if (t == 0) {
        *perp_out = expf(-red[0]);
        *loss_out = g_loss * (1.25f / (float)(NROWS * DDIM));
    }
}

extern "C" void kernel_launch(void* const* d_in, const int* in_sizes, int n_in,
                              void* d_out, int out_size)
{
    const float* z_e = (const float*)d_in[0];
    const float* emb = (const float*)d_in[1];
    float* out = (float*)d_out;

    cudaFuncSetAttribute(vq_main_kernel,
                         cudaFuncAttributeMaxDynamicSharedMemorySize, SMEM_BYTES);

    vq_prepack_kernel<<<65, 256>>>(emb);
    vq_main_kernel<<<GRID, NTHREADS, SMEM_BYTES>>>(
        z_e, emb, out + O_ZQ, out + O_IDX, out + O_DIST);
    vq_finalize_kernel<<<1, KCB>>>(out + O_LOSS, out + O_PERP);
}